// round 14
// baseline (speedup 1.0000x reference)
#include <cuda_runtime.h>

#define SX 512
#define NG (SX * SX)
#define NW (NG / 32)      // 8192 bitmap words (16 words per row)
#define MAXN 8192
#define TS 64             // tile size
#define NTX 8             // tiles per side

typedef unsigned long long u64;

// ---- persistent device state (self-cleaning across graph replays):
//  g_occ   : set in k_occ, cleared in k_out (not read there)
//  g_corb  : every word rewritten by k_tile each run (tile-exclusive words)
//  g_parent: rewritten at core cells each run; only core cells' entries read
//  g_cnt   : zeroed at core cells by k_tile (before k_raw adds)
//  g_rctr  : reset by k_occ (before k_raw appends, after prior k_out read)
//  g_raw/g_roots/g_pvox : stale entries unreachable (guarded by occ bits / R)
__device__ unsigned g_occ[NW];
__device__ unsigned g_corb[NW];
__device__ int g_parent[NG];
__device__ int g_raw[NG];       // occupied cell -> component-min root cell (or -1)
__device__ int g_cnt[NG];       // root cell -> voxel count (valid at core cells)
__device__ int g_roots[MAXN];   // collected root cell indices (unordered)
__device__ int g_pvox[MAXN];    // point -> voxel id
__device__ int g_rctr;          // number of roots R

// voxelization: must match jnp floor((p - (-51.2)) / 0.2) in fp32
__device__ __forceinline__ int voxel_of(float px, float py) {
    int cx = (int)floorf((px - (-51.2f)) / 0.2f);
    int cy = (int)floorf((py - (-51.2f)) / 0.2f);
    cx = min(max(cx, 0), SX - 1);
    cy = min(max(cy, 0), SX - 1);
    return cy * SX + cx;
}

__device__ __forceinline__ bool bit(const unsigned* bm, int v) {
    return (bm[v >> 5] >> (v & 31)) & 1u;
}

#define MAJ(a, b, c) (((a) & (b)) | ((a) & (c)) | ((b) & (c)))

// ---- global union-find (k_merge only; races quiesce at kernel boundary;
// min-hook by cell index => final roots are component minima, deterministic)
__device__ int ffind(int x) {
    while (true) {
        int p = g_parent[x];
        if (p == x) return x;
        int gp = g_parent[p];
        if (gp != p) g_parent[x] = gp;
        x = p;
    }
}
__device__ void funite(int a, int b) {
    int ra = ffind(a), rb = ffind(b);
    while (ra != rb) {
        if (ra < rb) { int t = ra; ra = rb; rb = t; }
        int prev = atomicCAS(&g_parent[ra], ra, rb);
        if (prev == ra) return;
        ra = ffind(prev);
        rb = ffind(rb);
    }
}
// read-only chase (parent static after k_merge => deterministic)
__device__ __forceinline__ int chase(int x) {
    int p = g_parent[x];
    while (p != x) { x = p; p = g_parent[x]; }
    return x;
}

// K1: voxelize points -> occ bitmap + pvox; reset root counter
__global__ void k_occ(const float* __restrict__ pts, int N) {
    int i = blockIdx.x * blockDim.x + threadIdx.x;
    if (i == 0) g_rctr = 0;
    if (i < N) {
        int v = voxel_of(pts[i * 5 + 1], pts[i * 5 + 2]);
        g_pvox[i] = v;
        atomicOr(&g_occ[v >> 5], 1u << (v & 31));
    }
}

// K2: per 64x64 tile: bit-parallel core computation + shared-memory local
//     union-find; writes g_corb (tile-exclusive words), g_parent (core cells
//     -> global index of tile-local component-min), g_cnt=0 at core cells.
__global__ void k_tile() {
    __shared__ u64 rowbits[TS + 2];          // occ rows gy0-1 .. gy0+64
    __shared__ unsigned char hl[TS + 2], hr[TS + 2];
    __shared__ u64 h0[TS + 2], h1[TS + 2];   // horizontal-sum bit planes
    __shared__ u64 corerow[TS];
    __shared__ unsigned short par[TS * TS];

    const int t = threadIdx.x;               // 256 threads
    const int tx = blockIdx.x & (NTX - 1), ty = blockIdx.x >> 3;
    const int gx0 = tx * TS, gy0 = ty * TS;

    // load occ rows (66 rows incl halo)
    if (t < TS + 2) {
        int gy = gy0 - 1 + t;
        u64 row = 0; unsigned char l = 0, r = 0;
        if ((unsigned)gy < SX) {
            int base = gy * 16 + tx * 2;
            row = (u64)g_occ[base] | ((u64)g_occ[base + 1] << 32);
            if (tx > 0)       l = (g_occ[base - 1] >> 31) & 1u;
            if (tx < NTX - 1) r = g_occ[base + 2] & 1u;
        }
        rowbits[t] = row; hl[t] = l; hr[t] = r;
    }
    __syncthreads();

    // horizontal 3-sum planes per row: value = h0 + 2*h1 in 0..3
    if (t < TS + 2) {
        u64 w = rowbits[t];
        u64 l = (w << 1) | (u64)hl[t];
        u64 r = (w >> 1) | ((u64)hr[t] << 63);
        h0[t] = l ^ w ^ r;
        h1[t] = MAJ(l, w, r);
    }
    __syncthreads();

    // vertical sum of 3 horizontal sums -> 4-bit planes; core = occ && sum>=5
    if (t < TS) {
        u64 a0 = h0[t],     a1 = h1[t];       // row above
        u64 b0 = h0[t + 1], b1 = h1[t + 1];   // this row
        u64 d0 = h0[t + 2], d1 = h1[t + 2];   // row below
        u64 c0 = a0 ^ b0, k0 = a0 & b0;
        u64 c1 = a1 ^ b1 ^ k0, c2 = MAJ(a1, b1, k0);
        u64 e0 = c0 ^ d0; k0 = c0 & d0;
        u64 e1 = c1 ^ d1 ^ k0; u64 k1 = MAJ(c1, d1, k0);
        u64 e2 = c2 ^ k1; u64 e3 = c2 & k1;
        u64 ge5 = e3 | (e2 & (e1 | e0));
        u64 core = rowbits[t + 1] & ge5;
        corerow[t] = core;
        int base = (gy0 + t) * 16 + tx * 2;   // tile-exclusive words
        g_corb[base]     = (unsigned)core;
        g_corb[base + 1] = (unsigned)(core >> 32);
    }
    __syncthreads();

    // init local parents at core cells
    for (int c = t; c < TS * TS; c += 256) {
        int y = c >> 6, x = c & 63;
        if ((corerow[y] >> x) & 1ull) par[c] = (unsigned short)c;
    }
    __syncthreads();

    // local unions over in-tile core-core back-edges (W, NW, N, NE)
    for (int c = t; c < TS * TS; c += 256) {
        int y = c >> 6, x = c & 63;
        if (!((corerow[y] >> x) & 1ull)) continue;
        // min-hook local union-find (final local roots = tile-local minima)
        auto lfind = [&](int z) -> int {
            while (true) {
                int p = par[z];
                if (p == z) return z;
                int gp = par[p];
                if (gp != p) par[z] = (unsigned short)gp;
                z = p;
            }
        };
        auto lunite = [&](int a, int b) {
            int ra = lfind(a), rb = lfind(b);
            while (ra != rb) {
                if (ra < rb) { int q = ra; ra = rb; rb = q; }
                unsigned short prev = atomicCAS(&par[ra], (unsigned short)ra, (unsigned short)rb);
                if (prev == (unsigned short)ra) return;
                ra = lfind(prev);
                rb = lfind(rb);
            }
        };
        if (x > 0 && ((corerow[y] >> (x - 1)) & 1ull)) lunite(c, c - 1);
        if (y > 0) {
            u64 up = corerow[y - 1];
            if (x > 0 && ((up >> (x - 1)) & 1ull)) lunite(c, c - 65);
            if ((up >> x) & 1ull)                  lunite(c, c - 64);
            if (x < 63 && ((up >> (x + 1)) & 1ull)) lunite(c, c - 63);
        }
    }
    __syncthreads();

    // flatten locally (read-only) -> global parent; clear counts at core cells
    for (int c = t; c < TS * TS; c += 256) {
        int y = c >> 6, x = c & 63;
        if (!((corerow[y] >> x) & 1ull)) continue;
        int z = c, p = par[z];
        while (p != z) { z = p; p = par[z]; }
        int gcell = (gy0 + y) * SX + gx0 + x;
        int groot = (gy0 + (z >> 6)) * SX + gx0 + (z & 63);
        g_parent[gcell] = groot;
        g_cnt[gcell] = 0;
    }
}

// K3: cross-tile unions (only boundary core cells; ~hundreds of edges)
__global__ void k_merge() {
    int tid = blockIdx.x * blockDim.x + threadIdx.x;   // 12288 threads
    int x, y;
    if (tid < 4096) {            // horizontal tile boundaries: y % 64 == 0
        y = (tid >> 9) * TS; x = tid & 511;
        if (y == 0) return;
        int v = y * SX + x;
        if (!bit(g_corb, v)) return;
        if (x > 0 && bit(g_corb, v - SX - 1)) funite(v, v - SX - 1);
        if (bit(g_corb, v - SX))              funite(v, v - SX);
        if (x < SX - 1 && bit(g_corb, v - SX + 1)) funite(v, v - SX + 1);
    } else if (tid < 8192) {     // vertical boundaries: x % 64 == 0 (W, NW)
        int k = tid - 4096;
        x = (k >> 9) * TS; y = k & 511;
        if (x == 0) return;
        int v = y * SX + x;
        if (!bit(g_corb, v)) return;
        if (bit(g_corb, v - 1)) funite(v, v - 1);
        if (y > 0 && (y & 63) != 0 && bit(g_corb, v - SX - 1)) funite(v, v - SX - 1);
    } else {                     // x % 64 == 63 (NE crossing right)
        int k = tid - 8192;
        x = (k >> 9) * TS + 63; y = k & 511;
        if (x >= SX - 1 || y == 0 || (y & 63) == 0) return;
        int v = y * SX + x;
        if (!bit(g_corb, v)) return;
        if (bit(g_corb, v - SX + 1)) funite(v, v - SX + 1);
    }
}

// K4: per occupied cell: raw root label (core: own root; border: min core-
//     neighbor root; else -1) + root collection + per-root voxel counts.
//     chase() is read-only on the now-static parent forest => deterministic.
__global__ void k_raw() {
    int i = blockIdx.x * blockDim.x + threadIdx.x;
    if (i >= NG) return;
    if (!bit(g_occ, i)) return;
    int r;
    if (bit(g_corb, i)) {
        r = chase(i);
        if (r == i) { int idx = atomicAdd(&g_rctr, 1); g_roots[idx] = i; }
    } else {
        int best = 0x7fffffff;
        int x = i & (SX - 1), y = i >> 9;
        #pragma unroll
        for (int dy = -1; dy <= 1; dy++) {
            int ny = y + dy;
            if ((unsigned)ny >= SX) continue;
            #pragma unroll
            for (int dx = -1; dx <= 1; dx++) {
                int nx = x + dx;
                if ((unsigned)nx >= SX) continue;
                int n = ny * SX + nx;
                if (bit(g_corb, n)) best = min(best, chase(n));
            }
        }
        r = (best == 0x7fffffff) ? -1 : best;
    }
    g_raw[i] = r;
    if (r >= 0) atomicAdd(&g_cnt[r], 1);
}

// K5: per-point final label (dense rank computed on the fly: rank of root
//     among all roots by cell index — order-invariant wrt append order);
//     block0 warp0: max_num_inst; cleanup of occ bitmap.
__global__ void k_out(int N, float* __restrict__ out, int out_size) {
    int i = blockIdx.x * blockDim.x + threadIdx.x;
    int R = g_rctr;
    if (i < N) {
        int v = g_pvox[i];
        int r = g_raw[v];
        float f = -1.0f;
        if (r >= 0 && g_cnt[r] >= 20) {
            int rank = 0;
            for (int j = 0; j < R; j++) rank += (g_roots[j] < r);
            f = (float)rank;
        }
        out[i] = f;
    }
    if (i < NW) g_occ[i] = 0;      // cleanup (occ not read in this kernel)
    if (blockIdx.x == 0 && threadIdx.x < 32) {
        int lane = threadIdx.x;
        int m = 0;
        for (int j = lane; j < R; j += 32) {
            int rj = g_roots[j];
            if (g_cnt[rj] >= 20) {
                int rank = 0;
                for (int k = 0; k < R; k++) rank += (g_roots[k] < rj);
                m = max(m, rank + 1);
            }
        }
        m = __reduce_max_sync(0xffffffffu, m);
        if (lane == 0 && out_size > N) out[N] = (float)m;
    }
}

extern "C" void kernel_launch(void* const* d_in, const int* in_sizes, int n_in,
                              void* d_out, int out_size) {
    const float* pts = (const float*)d_in[0];
    int N = in_sizes[0] / 5;
    if (N > MAXN) N = MAXN;
    float* out = (float*)d_out;

    const int T = 256;
    k_occ  <<<(MAXN + T - 1) / T, T>>>(pts, N);
    k_tile <<<NTX * NTX, T>>>();
    k_merge<<<(12288 + T - 1) / T, T>>>();
    k_raw  <<<(NG + T - 1) / T, T>>>();
    k_out  <<<(MAXN + T - 1) / T, T>>>(N, out, out_size);
}

// round 15
// speedup vs baseline: 1.0793x; 1.0793x over previous
#include <cuda_runtime.h>

#define SX 512
#define NG (SX * SX)
#define NW (NG / 32)      // 8192 bitmap words, 16 per row
#define MAXN 8192
typedef unsigned u32;

// ---- persistent device state (self-cleaning across graph replays):
//  g_occ   : set in k_occ (atomicOr), cleared in k_out (not read there)
//  g_corb  : EVERY word rewritten non-atomically by k_cores each run
//  g_parent: rewritten at core cells by k_init; only core cells read
//  g_cnt   : zeroed at core cells by k_init; only root (core) cells read
//  g_rctr  : reset in k_occ (before k_raw appends, after prior k_out read)
//  g_raw/g_roots/g_pvox : stale entries unreachable (guarded by fresh occ/R)
__device__ u32 g_occ[NW];
__device__ u32 g_corb[NW];
__device__ int g_parent[NG];
__device__ int g_raw[NG];       // occupied cell -> component-min root (or -1)
__device__ int g_cnt[NG];       // root cell -> voxel count
__device__ int g_roots[MAXN];   // root cell indices (unordered)
__device__ int g_pvox[MAXN];    // point -> voxel id
__device__ int g_rctr;

#define MAJ(a, b, c) (((a) & (b)) | ((a) & (c)) | ((b) & (c)))

// voxelization: must match jnp floor((p - (-51.2)) / 0.2) in fp32
__device__ __forceinline__ int voxel_of(float px, float py) {
    int cx = (int)floorf((px - (-51.2f)) / 0.2f);
    int cy = (int)floorf((py - (-51.2f)) / 0.2f);
    cx = min(max(cx, 0), SX - 1);
    cy = min(max(cy, 0), SX - 1);
    return cy * SX + cx;
}

__device__ __forceinline__ bool bit(const u32* bm, int v) {
    return (bm[v >> 5] >> (v & 31)) & 1u;
}

// ---- global union-find (k_union only; races quiesce at kernel boundary;
// min-hook by cell index => final roots are component minima, deterministic)
__device__ int ffind(int x) {
    while (true) {
        int p = g_parent[x];
        if (p == x) return x;
        int gp = g_parent[p];
        if (gp != p) g_parent[x] = gp;   // path halving (benign race)
        x = p;
    }
}
__device__ void funite(int a, int b) {
    int ra = ffind(a), rb = ffind(b);
    while (ra != rb) {
        if (ra < rb) { int t = ra; ra = rb; rb = t; }
        int prev = atomicCAS(&g_parent[ra], ra, rb);
        if (prev == ra) return;
        ra = ffind(prev);
        rb = ffind(rb);
    }
}
// read-only chase (parent static after k_union => deterministic)
__device__ __forceinline__ int chase(int x) {
    int p = g_parent[x];
    while (p != x) { x = p; p = g_parent[x]; }
    return x;
}

// neighbor-core masks for word w (valid after k_cores):
// bit b set in Wm/Nm/NWm/NEm  <=>  that neighbor of cell b is core
__device__ __forceinline__ void nbr_masks(int w, u32& Wm, u32& Nm, u32& NWm, u32& NEm) {
    int wx = w & 15, y = w >> 4;
    u32 cw = g_corb[w];
    u32 cl = (wx > 0) ? g_corb[w - 1] : 0;
    u32 au = 0, al = 0, ar = 0;
    if (y > 0) {
        au = g_corb[w - 16];
        if (wx > 0)  al = g_corb[w - 17];
        if (wx < 15) ar = g_corb[w - 15];
    }
    Wm  = (cw << 1) | (cl >> 31);
    Nm  = au;
    NWm = (au << 1) | (al >> 31);
    NEm = (au >> 1) | (ar << 31);
}

// K1: voxelize -> occ bitmap + pvox; reset root counter
__global__ void k_occ(const float* __restrict__ pts, int N) {
    int i = blockIdx.x * blockDim.x + threadIdx.x;
    if (i == 0) g_rctr = 0;
    if (i < N) {
        int v = voxel_of(pts[i * 5 + 1], pts[i * 5 + 2]);
        g_pvox[i] = v;
        atomicOr(&g_occ[v >> 5], 1u << (v & 31));
    }
}

// K2: bit-parallel core word (>=5 occupied in 3x3 incl self; eps=1.5 =>
// 8-neighborhood). One thread owns one corb word: non-atomic write.
__global__ void k_cores() {
    int w = blockIdx.x * blockDim.x + threadIdx.x;
    if (w >= NW) return;
    int wx = w & 15, y = w >> 4;
    u32 h0[3], h1[3], mid = 0;
    #pragma unroll
    for (int d = 0; d < 3; d++) {
        int ry = y - 1 + d;
        u32 m = 0, lw = 0, rw = 0;
        if ((unsigned)ry < SX) {
            int base = ry * 16 + wx;
            m = g_occ[base];
            if (wx > 0)  lw = g_occ[base - 1];
            if (wx < 15) rw = g_occ[base + 1];
        }
        if (d == 1) mid = m;
        u32 l = (m << 1) | (lw >> 31);
        u32 r = (m >> 1) | (rw << 31);
        h0[d] = l ^ m ^ r;
        h1[d] = MAJ(l, m, r);
    }
    // sum of three 2-bit horizontal counts -> 4-bit planes; ge5 test
    u32 c0 = h0[0] ^ h0[1], k0 = h0[0] & h0[1];
    u32 c1 = h1[0] ^ h1[1] ^ k0, c2 = MAJ(h1[0], h1[1], k0);
    u32 e0 = c0 ^ h0[2]; k0 = c0 & h0[2];
    u32 e1 = c1 ^ h1[2] ^ k0; u32 k1 = MAJ(c1, h1[2], k0);
    u32 e2 = c2 ^ k1, e3 = c2 & k1;
    u32 ge5 = e3 | (e2 & (e1 | e0));
    g_corb[w] = mid & ge5;
}

// K3: ECL-CC-style init: parent[i] = min core back-neighbor (or self);
// pure function of corb, non-atomic own-cell writes => deterministic forest
// with strictly decreasing parents. Also zero counts at core cells.
__global__ void k_init() {
    int w = blockIdx.x * blockDim.x + threadIdx.x;
    if (w >= NW) return;
    u32 cw = g_corb[w];
    if (!cw) return;
    u32 Wm, Nm, NWm, NEm;
    nbr_masks(w, Wm, Nm, NWm, NEm);
    int rowbase = (w >> 4) * SX + (w & 15) * 32;
    u32 bits = cw;
    while (bits) {
        int b = __ffs(bits) - 1; bits &= bits - 1;
        int i = rowbase + b;
        int mn = i;                                   // priority: smallest index
        if      ((NWm >> b) & 1) mn = i - SX - 1;
        else if ((Nm  >> b) & 1) mn = i - SX;
        else if ((NEm >> b) & 1) mn = i - SX + 1;
        else if ((Wm  >> b) & 1) mn = i - 1;
        g_parent[i] = mn;
        g_cnt[i] = 0;
    }
}

// K4: hooking over all core-core back-edges. Min-init already linked most of
// each component, so finds are short and CAS contention is rare.
__global__ void k_union() {
    int w = blockIdx.x * blockDim.x + threadIdx.x;
    if (w >= NW) return;
    u32 cw = g_corb[w];
    if (!cw) return;
    u32 Wm, Nm, NWm, NEm;
    nbr_masks(w, Wm, Nm, NWm, NEm);
    u32 any = cw & (Wm | Nm | NWm | NEm);
    int rowbase = (w >> 4) * SX + (w & 15) * 32;
    while (any) {
        int b = __ffs(any) - 1; any &= any - 1;
        int i = rowbase + b;
        if ((Wm  >> b) & 1) funite(i, i - 1);
        if ((NWm >> b) & 1) funite(i, i - SX - 1);
        if ((Nm  >> b) & 1) funite(i, i - SX);
        if ((NEm >> b) & 1) funite(i, i - SX + 1);
    }
}

// K5: per occupied cell (nibble-parallel): raw root label + root collection
// + per-root voxel counts. chase() is read-only on static parent.
__global__ void k_raw() {
    int t = blockIdx.x * blockDim.x + threadIdx.x;   // 65536 threads
    if (t >= NW * 8) return;
    int w = t >> 3, nib = t & 7;
    u32 nb = (g_occ[w] >> (nib * 4)) & 0xFu;
    if (!nb) return;
    u32 cw = g_corb[w];
    int rowbase = (w >> 4) * SX + (w & 15) * 32 + nib * 4;
    while (nb) {
        int b = __ffs(nb) - 1; nb &= nb - 1;
        int i = rowbase + b;
        int r;
        if ((cw >> (nib * 4 + b)) & 1) {
            r = chase(i);
            if (r == i) { int idx = atomicAdd(&g_rctr, 1); g_roots[idx] = i; }
        } else {
            int best = 0x7fffffff;
            int x = i & (SX - 1), y = i >> 9;
            #pragma unroll
            for (int dy = -1; dy <= 1; dy++) {
                int ny = y + dy;
                if ((unsigned)ny >= SX) continue;
                #pragma unroll
                for (int dx = -1; dx <= 1; dx++) {
                    int nx = x + dx;
                    if ((unsigned)nx >= SX) continue;
                    int n = ny * SX + nx;
                    if (bit(g_corb, n)) best = min(best, chase(n));
                }
            }
            r = (best == 0x7fffffff) ? -1 : best;
        }
        g_raw[i] = r;
        if (r >= 0) atomicAdd(&g_cnt[r], 1);
    }
}

// K6: per-point final label (dense rank of root among all roots by cell
// index — order-invariant); block0 warp0: max_num_inst; clear occ bitmap.
__global__ void k_out(int N, float* __restrict__ out, int out_size) {
    int i = blockIdx.x * blockDim.x + threadIdx.x;
    int R = g_rctr;
    if (i < N) {
        int v = g_pvox[i];
        int r = g_raw[v];
        float f = -1.0f;
        if (r >= 0 && g_cnt[r] >= 20) {
            int rank = 0;
            for (int j = 0; j < R; j++) rank += (g_roots[j] < r);
            f = (float)rank;
        }
        out[i] = f;
    }
    if (i < NW) g_occ[i] = 0;      // cleanup (occ not read in this kernel)
    if (blockIdx.x == 0 && threadIdx.x < 32) {
        int lane = threadIdx.x;
        int m = 0;
        for (int j = lane; j < R; j += 32) {
            int rj = g_roots[j];
            if (g_cnt[rj] >= 20) {
                int rank = 0;
                for (int k = 0; k < R; k++) rank += (g_roots[k] < rj);
                m = max(m, rank + 1);
            }
        }
        m = __reduce_max_sync(0xffffffffu, m);
        if (lane == 0 && out_size > N) out[N] = (float)m;
    }
}

extern "C" void kernel_launch(void* const* d_in, const int* in_sizes, int n_in,
                              void* d_out, int out_size) {
    const float* pts = (const float*)d_in[0];
    int N = in_sizes[0] / 5;
    if (N > MAXN) N = MAXN;
    float* out = (float*)d_out;

    const int T = 256;
    const int WB = (NW + T - 1) / T;          // 32 blocks: word-parallel passes
    k_occ  <<<(MAXN + T - 1) / T, T>>>(pts, N);
    k_cores<<<WB, T>>>();
    k_init <<<WB, T>>>();
    k_union<<<WB, T>>>();
    k_raw  <<<(NW * 8 + T - 1) / T, T>>>();
    k_out  <<<(MAXN + T - 1) / T, T>>>(N, out, out_size);
}

// round 16
// speedup vs baseline: 1.3607x; 1.2608x over previous
#include <cuda_runtime.h>

#define SX 512
#define NG (SX * SX)
#define NW (NG / 32)      // 8192 bitmap words, 16 per row
#define MAXN 8192
typedef unsigned u32;

// ---- persistent device state (self-cleaning across graph replays):
//  g_occ   : set in k_occ (atomicOr), cleared in k_out (not read there)
//  g_corb  : EVERY word rewritten non-atomically by k_coreinit each run
//  g_parent: rewritten at core cells by k_coreinit; only core cells read
//  g_cnt   : zeroed at core cells by k_coreinit; read/written only at core cells
//  g_rctr  : reset in k_occ (before k_flat appends, after prior k_out read)
//  g_raw   : written at every occupied cell each run (k_flat/k_border)
//  g_roots/g_pvox : stale entries unreachable (guarded by fresh R / N)
__device__ u32 g_occ[NW];
__device__ u32 g_corb[NW];
__device__ int g_parent[NG];
__device__ int g_raw[NG];       // occupied cell -> component-min root (or -1)
__device__ int g_cnt[NG];       // root cell -> voxel count
__device__ int g_roots[MAXN];   // root cell indices (unordered)
__device__ int g_pvox[MAXN];    // point -> voxel id
__device__ int g_rctr;

#define MAJ(a, b, c) (((a) & (b)) | ((a) & (c)) | ((b) & (c)))

// voxelization: must match jnp floor((p - (-51.2)) / 0.2) in fp32
__device__ __forceinline__ int voxel_of(float px, float py) {
    int cx = (int)floorf((px - (-51.2f)) / 0.2f);
    int cy = (int)floorf((py - (-51.2f)) / 0.2f);
    cx = min(max(cx, 0), SX - 1);
    cy = min(max(cy, 0), SX - 1);
    return cy * SX + cx;
}

__device__ __forceinline__ bool bit(const u32* bm, int v) {
    return (bm[v >> 5] >> (v & 31)) & 1u;
}

// bit-parallel core word at (wx, y): cell is core iff occupied and its 3x3
// neighborhood (self incl) has >=5 occupied (eps=1.5 => 8-neighborhood).
// Exact same adder algebra as the R15 k_cores (verified correct).
__device__ u32 core_word(int wx, int y) {
    if ((unsigned)wx >= 16u || (unsigned)y >= (unsigned)SX) return 0u;
    u32 h0[3], h1[3], mid = 0;
    #pragma unroll
    for (int d = 0; d < 3; d++) {
        int ry = y - 1 + d;
        u32 m = 0, lw = 0, rw = 0;
        if ((unsigned)ry < (unsigned)SX) {
            int base = ry * 16 + wx;
            m = g_occ[base];
            if (wx > 0)  lw = g_occ[base - 1];
            if (wx < 15) rw = g_occ[base + 1];
        }
        if (d == 1) mid = m;
        u32 l = (m << 1) | (lw >> 31);
        u32 r = (m >> 1) | (rw << 31);
        h0[d] = l ^ m ^ r;
        h1[d] = MAJ(l, m, r);
    }
    u32 c0 = h0[0] ^ h0[1], k0 = h0[0] & h0[1];
    u32 c1 = h1[0] ^ h1[1] ^ k0, c2 = MAJ(h1[0], h1[1], k0);
    u32 e0 = c0 ^ h0[2]; k0 = c0 & h0[2];
    u32 e1 = c1 ^ h1[2] ^ k0; u32 k1 = MAJ(c1, h1[2], k0);
    u32 e2 = c2 ^ k1, e3 = c2 & k1;
    u32 ge5 = e3 | (e2 & (e1 | e0));
    return mid & ge5;
}

// ---- union-find (k_union only; races quiesce at kernel boundary; min-hook
// by cell index => final roots are component minima, deterministic)
__device__ int ffind(int x) {
    while (true) {
        int p = g_parent[x];
        if (p == x) return x;
        int gp = g_parent[p];
        if (gp != p) g_parent[x] = gp;   // path halving (benign race)
        x = p;
    }
}
__device__ void funite(int a, int b) {
    int ra = ffind(a), rb = ffind(b);
    while (ra != rb) {
        if (ra < rb) { int t = ra; ra = rb; rb = t; }
        int prev = atomicCAS(&g_parent[ra], ra, rb);
        if (prev == ra) return;
        ra = ffind(prev);
        rb = ffind(rb);
    }
}
// read-only chase (parent static after k_union => deterministic)
__device__ __forceinline__ int chase(int x) {
    int p = g_parent[x];
    while (p != x) { x = p; p = g_parent[x]; }
    return x;
}

// K1: voxelize -> occ bitmap + pvox; reset root counter
__global__ void k_occ(const float* __restrict__ pts, int N) {
    int i = blockIdx.x * blockDim.x + threadIdx.x;
    if (i == 0) g_rctr = 0;
    if (i < N) {
        int v = voxel_of(pts[i * 5 + 1], pts[i * 5 + 2]);
        g_pvox[i] = v;
        atomicOr(&g_occ[v >> 5], 1u << (v & 31));
    }
}

// K2: core bitmap + ECL-CC min-init, fused. Thread owns word w; recomputes
// the 4 neighbor core words from occ (pure function -> no race). parent[i] =
// min core back-neighbor (or self); deterministic decreasing forest.
__global__ void k_coreinit() {
    int w = blockIdx.x * blockDim.x + threadIdx.x;
    if (w >= NW) return;
    int wx = w & 15, y = w >> 4;
    u32 cw = core_word(wx, y);
    g_corb[w] = cw;                    // every word rewritten
    if (!cw) return;
    u32 cl = core_word(wx - 1, y);
    u32 au = core_word(wx, y - 1);
    u32 al = core_word(wx - 1, y - 1);
    u32 ar = core_word(wx + 1, y - 1);
    u32 Wm  = (cw << 1) | (cl >> 31);
    u32 Nm  = au;
    u32 NWm = (au << 1) | (al >> 31);
    u32 NEm = (au >> 1) | (ar << 31);
    int rowbase = y * SX + wx * 32;
    u32 bits = cw;
    while (bits) {
        int b = __ffs(bits) - 1; bits &= bits - 1;
        int i = rowbase + b;
        int mn = i;
        if      ((NWm >> b) & 1) mn = i - SX - 1;   // smallest-index neighbor
        else if ((Nm  >> b) & 1) mn = i - SX;
        else if ((NEm >> b) & 1) mn = i - SX + 1;
        else if ((Wm  >> b) & 1) mn = i - 1;
        g_parent[i] = mn;
        g_cnt[i] = 0;
    }
}

// K3: per-cell hooking over core-core back-edges. Min-init pre-linked almost
// everything, so finds are 1-2 hops and CAS merges are rare.
__global__ void k_union() {
    int i = blockIdx.x * blockDim.x + threadIdx.x;
    if (i >= NG) return;
    if (!bit(g_corb, i)) return;
    int x = i & (SX - 1), y = i >> 9;
    if (x > 0 && bit(g_corb, i - 1)) funite(i, i - 1);
    if (y > 0) {
        if (x > 0 && bit(g_corb, i - SX - 1)) funite(i, i - SX - 1);
        if (bit(g_corb, i - SX))              funite(i, i - SX);
        if (x < SX - 1 && bit(g_corb, i - SX + 1)) funite(i, i - SX + 1);
    }
}

// K4: core cells: read-only chase -> g_raw; collect roots; count own voxel
__global__ void k_flat() {
    int i = blockIdx.x * blockDim.x + threadIdx.x;
    if (i >= NG) return;
    if (!bit(g_corb, i)) return;
    int r = chase(i);
    g_raw[i] = r;
    if (r == i) { int idx = atomicAdd(&g_rctr, 1); g_roots[idx] = i; }
    atomicAdd(&g_cnt[r], 1);
}

// K5: border (occupied, non-core) cells: min over core neighbors' g_raw
// (single loads — no chasing); count its voxel into that cluster.
__global__ void k_border() {
    int i = blockIdx.x * blockDim.x + threadIdx.x;
    if (i >= NG) return;
    if (!bit(g_occ, i) || bit(g_corb, i)) return;
    int best = 0x7fffffff;
    int x = i & (SX - 1), y = i >> 9;
    #pragma unroll
    for (int dy = -1; dy <= 1; dy++) {
        int ny = y + dy;
        if ((unsigned)ny >= SX) continue;
        #pragma unroll
        for (int dx = -1; dx <= 1; dx++) {
            int nx = x + dx;
            if ((unsigned)nx >= SX) continue;
            int n = ny * SX + nx;
            if (bit(g_corb, n)) best = min(best, g_raw[n]);
        }
    }
    int r = (best == 0x7fffffff) ? -1 : best;
    g_raw[i] = r;
    if (r >= 0) atomicAdd(&g_cnt[r], 1);
}

// K6: per-point final label (dense rank of root among all roots by cell
// index — append-order-invariant); block0 warp0: max_num_inst; clear occ.
__global__ void k_out(int N, float* __restrict__ out, int out_size) {
    int i = blockIdx.x * blockDim.x + threadIdx.x;
    int R = g_rctr;
    if (i < N) {
        int v = g_pvox[i];
        int r = g_raw[v];
        float f = -1.0f;
        if (r >= 0 && g_cnt[r] >= 20) {
            int rank = 0;
            for (int j = 0; j < R; j++) rank += (g_roots[j] < r);
            f = (float)rank;
        }
        out[i] = f;
    }
    if (i < NW) g_occ[i] = 0;          // cleanup (occ not read in this kernel)
    if (blockIdx.x == 0 && threadIdx.x < 32) {
        int lane = threadIdx.x;
        int m = 0;
        for (int j = lane; j < R; j += 32) {
            int rj = g_roots[j];
            if (g_cnt[rj] >= 20) {
                int rank = 0;
                for (int k = 0; k < R; k++) rank += (g_roots[k] < rj);
                m = max(m, rank + 1);
            }
        }
        m = __reduce_max_sync(0xffffffffu, m);
        if (lane == 0 && out_size > N) out[N] = (float)m;
    }
}

extern "C" void kernel_launch(void* const* d_in, const int* in_sizes, int n_in,
                              void* d_out, int out_size) {
    const float* pts = (const float*)d_in[0];
    int N = in_sizes[0] / 5;
    if (N > MAXN) N = MAXN;
    float* out = (float*)d_out;

    const int T = 256;
    const int GB = (NG + T - 1) / T;      // 1024 blocks: per-cell passes
    const int WB = (NW + T - 1) / T;      // 32 blocks: word-parallel pass
    k_occ     <<<(MAXN + T - 1) / T, T>>>(pts, N);
    k_coreinit<<<WB, T>>>();
    k_union   <<<GB, T>>>();
    k_flat    <<<GB, T>>>();
    k_border  <<<GB, T>>>();
    k_out     <<<(MAXN + T - 1) / T, T>>>(N, out, out_size);
}